// round 17
// baseline (speedup 1.0000x reference)
#include <cuda_runtime.h>
#include <math.h>
#include <stdint.h>

// SE(3) exp + point transform, single kernel, NO block barrier, NO shfl.
// out[bt,n,:] = R(dofs[bt]) * X[bt,n,:] + t(dofs[bt])
// X_v: [B,T,N,3] f32, dofs: [B,T,6] f32, out: [B,T,N,3] f32. B=64,T=28,N=4096.
//
// This round: 256-bit memory ops (ld/st.global .v8.b32, sm_103a). Each
// thread handles 8 points = 96B = 3x 32B chunks -> 3 LDG.256 + 3 STG.256,
// halving memory-instruction and L1tex-request count vs float4. Direct
// L2::evict_first (loads) / evict_last (stores) modifiers are legal on v8.
// Discriminates: LTS-cap (neutral) vs instruction-overhead (win) vs
// lines-in-flight (regression, like R7).

#define THREADS 256
#define TILES_PER_SLICE 512     // N / 8 pts per tile

__device__ __forceinline__ void ldg256(const float* p, float v[8]) {
    uint32_t r0,r1,r2,r3,r4,r5,r6,r7;
    asm volatile("ld.global.nc.L2::evict_first.v8.b32 {%0,%1,%2,%3,%4,%5,%6,%7}, [%8];"
                 : "=r"(r0),"=r"(r1),"=r"(r2),"=r"(r3),
                   "=r"(r4),"=r"(r5),"=r"(r6),"=r"(r7)
                 : "l"(p));
    v[0]=__uint_as_float(r0); v[1]=__uint_as_float(r1);
    v[2]=__uint_as_float(r2); v[3]=__uint_as_float(r3);
    v[4]=__uint_as_float(r4); v[5]=__uint_as_float(r5);
    v[6]=__uint_as_float(r6); v[7]=__uint_as_float(r7);
}

__device__ __forceinline__ void stg256(float* p, const float v[8]) {
    asm volatile("st.global.L2::evict_last.v8.b32 [%0], {%1,%2,%3,%4,%5,%6,%7,%8};"
                 :: "l"(p),
                    "r"(__float_as_uint(v[0])), "r"(__float_as_uint(v[1])),
                    "r"(__float_as_uint(v[2])), "r"(__float_as_uint(v[3])),
                    "r"(__float_as_uint(v[4])), "r"(__float_as_uint(v[5])),
                    "r"(__float_as_uint(v[6])), "r"(__float_as_uint(v[7]))
                 : "memory");
}

__global__ void __launch_bounds__(THREADS)
se3_transform_kernel(const float* __restrict__ X,
                     const float* __restrict__ dofs,
                     float* __restrict__ out)
{
    // 1 tile = 8 points = 24 floats = 96 bytes (32B-aligned: 96 % 32 == 0).
    // 512 tiles per bt slice; warp spans 32 consecutive tiles -> one bt/warp.
    const unsigned tile = blockIdx.x * THREADS + threadIdx.x;
    const unsigned bt   = tile >> 9;

    const float* src = X   + (size_t)tile * 24;
    float*       dst = out + (size_t)tile * 24;

    // ---- issue 3x 256-bit loads FIRST (independent of R,t) ----
    float A[8], B[8], C[8];
    ldg256(src +  0, A);
    ldg256(src +  8, B);
    ldg256(src + 16, C);

    // ---- fast SE(3) prologue, all lanes (hidden under load latency) ----
    const float* d = dofs + bt * 6;
    const float tx = __ldg(&d[0]), ty = __ldg(&d[1]), tz = __ldg(&d[2]);
    const float wx = __ldg(&d[3]), wy = __ldg(&d[4]), wz = __ldg(&d[5]);

    const float nrm   = wx*wx + wy*wy + wz*wz;
    const float th2c  = fmaxf(nrm, 1.0e-4f);     // clip BEFORE sqrt (matches ref)
    const float inv_t = rsqrtf(th2c);
    const float theta = th2c * inv_t;

    const float s2 = __sinf(0.5f * theta);
    const float c2 = __cosf(0.5f * theta);
    const float st = 2.0f * s2 * c2;

    const float inv_t2 = inv_t * inv_t;
    const float f1 = st * inv_t;
    const float f2 = 2.0f * s2 * s2 * inv_t2;
    const float f3 = (theta - st) * inv_t2 * inv_t;

    const float h2xx = wx*wx - nrm, h2yy = wy*wy - nrm, h2zz = wz*wz - nrm;
    const float h2xy = wx*wy, h2xz = wx*wz, h2yz = wy*wz;

    const float r00 = 1.0f + f2*h2xx;
    const float r01 = -f1*wz + f2*h2xy;
    const float r02 =  f1*wy + f2*h2xz;
    const float r10 =  f1*wz + f2*h2xy;
    const float r11 = 1.0f + f2*h2yy;
    const float r12 = -f1*wx + f2*h2yz;
    const float r20 = -f1*wy + f2*h2xz;
    const float r21 =  f1*wx + f2*h2yz;
    const float r22 = 1.0f + f2*h2zz;

    const float v00 = 1.0f + f3*h2xx;
    const float v01 = -f2*wz + f3*h2xy;
    const float v02 =  f2*wy + f3*h2xz;
    const float v10 =  f2*wz + f3*h2xy;
    const float v11 = 1.0f + f3*h2yy;
    const float v12 = -f2*wx + f3*h2yz;
    const float v20 = -f2*wy + f3*h2xz;
    const float v21 =  f2*wx + f3*h2yz;
    const float v22 = 1.0f + f3*h2zz;

    const float t0 = v00*tx + v01*ty + v02*tz;
    const float t1 = v10*tx + v11*ty + v12*tz;
    const float t2 = v20*tx + v21*ty + v22*tz;

    // ---- transform 8 points; layout:
    // A: p0=(A0,A1,A2) p1=(A3,A4,A5) p2xy=(A6,A7)
    // B: p2z=B0 p3=(B1,B2,B3) p4=(B4,B5,B6) p5x=B7
    // C: p5yz=(C0,C1) p6=(C2,C3,C4) p7=(C5,C6,C7)
#define XF(ox,oy,oz, px,py,pz)                                          \
    ox = fmaf(r00,(px), fmaf(r01,(py), fmaf(r02,(pz), t0)));            \
    oy = fmaf(r10,(px), fmaf(r11,(py), fmaf(r12,(pz), t1)));            \
    oz = fmaf(r20,(px), fmaf(r21,(py), fmaf(r22,(pz), t2)));

    float OA[8], OB[8], OC[8];
    XF(OA[0],OA[1],OA[2], A[0],A[1],A[2]);          // p0
    XF(OA[3],OA[4],OA[5], A[3],A[4],A[5]);          // p1
    XF(OA[6],OA[7],OB[0], A[6],A[7],B[0]);          // p2
    XF(OB[1],OB[2],OB[3], B[1],B[2],B[3]);          // p3
    XF(OB[4],OB[5],OB[6], B[4],B[5],B[6]);          // p4
    XF(OB[7],OC[0],OC[1], B[7],C[0],C[1]);          // p5
    XF(OC[2],OC[3],OC[4], C[2],C[3],C[4]);          // p6
    XF(OC[5],OC[6],OC[7], C[5],C[6],C[7]);          // p7
#undef XF

    stg256(dst +  0, OA);
    stg256(dst +  8, OB);
    stg256(dst + 16, OC);
}

extern "C" void kernel_launch(void* const* d_in, const int* in_sizes, int n_in,
                              void* d_out, int out_size)
{
    const float* X    = (const float*)d_in[0];   // [B,T,N,3]
    const float* dofs = (const float*)d_in[1];   // [B,T,6]

    const int nBT = in_sizes[1] / 6;             // 1792
    const int N   = (in_sizes[0] / nBT) / 3;     // 4096

    const int totalTiles = nBT * (N / 8);        // 1792 * 512
    const int blocks = totalTiles / THREADS;     // 3584

    se3_transform_kernel<<<blocks, THREADS>>>(X, dofs, (float*)d_out);
}